// round 5
// baseline (speedup 1.0000x reference)
#include <cuda_runtime.h>

// Problem constants
#define BB     32
#define HQ     32
#define HKV    8
#define DD     128
#define SS     4096
#define GG     4          // HQ / HKV
#define NSPLIT 16         // interleaved: split i takes tokens s ≡ i (mod 16)
#define NWARP  4
#define NTHR   128
#define TT     4                  // tokens per warp per iteration
#define STRIDE (TT * NWARP)       // 16 token-slots per CTA iteration

// Split-KV partial scratch (allocation-free: __device__ globals)
__device__ float g_pacc[(size_t)NSPLIT * BB * HQ * DD];   // 8.4 MB
__device__ float g_pl[NSPLIT * BB * HQ];
__device__ unsigned int g_cnt[BB * HKV];                  // zero-init; self-resetting

__device__ __forceinline__ float dot4(float4 a, float4 b) {
    return a.x*b.x + a.y*b.y + a.z*b.z + a.w*b.w;
}

__global__ __launch_bounds__(NTHR, 4) void attn_fused(
    const float* __restrict__ xq, const float* __restrict__ xk,
    const float* __restrict__ xv, const float* __restrict__ kv,
    const int* __restrict__ cur_sel, const int* __restrict__ table,
    const int* __restrict__ seqlens, float* __restrict__ out)
{
    const int split = blockIdx.x;
    const int h     = blockIdx.y;
    const int b     = blockIdx.z;

    const int seq_len = seqlens[b];
    // Interleaved split: tokens s = split + NSPLIT * t, t in [0, nt).
    // seq_len >= 1024 > NSPLIT, so nt >= 64: every split is always active.
    const int nt  = (seq_len - split + NSPLIT - 1) / NSPLIT;
    const int cur = cur_sel[b];

    const int tid  = threadIdx.x;
    const int wid  = tid >> 5;
    const int lane = tid & 31;
    const bool sel1 = lane & 1;
    const bool sel2 = lane & 2;
    const int  bcast_base = lane & 28;

    __shared__ float sh_acc[NWARP][GG][DD];   // 8 KB
    __shared__ float sh_l[NWARP][GG];
    __shared__ unsigned int sh_ticket;

    // softmax in log2 domain; fold scale*log2e into Q
    const float scale = 0.08838834764831845f * 1.4426950408889634f;
    float4 qv[GG];
#pragma unroll
    for (int g = 0; g < GG; g++) {
        float4 q = *(const float4*)(xq + ((size_t)b * HQ + h * GG + g) * DD + lane * 4);
        q.x *= scale; q.y *= scale; q.z *= scale; q.w *= scale;
        qv[g] = q;
    }

    float  l[GG];
    float4 acc[GG];
#pragma unroll
    for (int g = 0; g < GG; g++) { l[g] = 0.f; acc[g] = make_float4(0.f,0.f,0.f,0.f); }

    const int    tbase = b * SS;
    const size_t qkvo  = ((size_t)b * HKV + h) * DD;
    const size_t rowsz = (size_t)(2 * HKV * DD);
    const size_t koff  = (size_t)h * DD;
    const size_t voff  = (size_t)(HKV + h) * DD;

    const int t0 = TT * wid;
    const int tmax = nt - 1;

    float4 ck[TT], cv[TT];    // K/V in flight for the *next* iteration
    int    nr[TT];            // row indices two iterations ahead

    if (t0 < nt) {
#pragma unroll
        for (int j = 0; j < TT; j++) {
            int s = split + NSPLIT * min(t0 + j, tmax);
            int r = __ldg(table + tbase + s);
            const float* kp = (r == cur) ? xk + qkvo : kv + (size_t)r * rowsz + koff;
            const float* vp = (r == cur) ? xv + qkvo : kv + (size_t)r * rowsz + voff;
            ck[j] = *(const float4*)(kp + lane * 4);
            cv[j] = *(const float4*)(vp + lane * 4);
        }
#pragma unroll
        for (int j = 0; j < TT; j++)
            nr[j] = __ldg(table + tbase + split + NSPLIT * min(t0 + STRIDE + j, tmax));
    }

    for (int t = t0; t < nt; t += STRIDE) {
        float4 k[TT], v[TT];
#pragma unroll
        for (int j = 0; j < TT; j++) { k[j] = ck[j]; v[j] = cv[j]; }

        if (t + STRIDE < nt) {
            // issue next iteration's K/V from prefetched row indices
#pragma unroll
            for (int j = 0; j < TT; j++) {
                int r = nr[j];
                const float* kp = (r == cur) ? xk + qkvo : kv + (size_t)r * rowsz + koff;
                const float* vp = (r == cur) ? xv + qkvo : kv + (size_t)r * rowsz + voff;
                ck[j] = *(const float4*)(kp + lane * 4);
                cv[j] = *(const float4*)(vp + lane * 4);
            }
            // row indices two iterations ahead
#pragma unroll
            for (int j = 0; j < TT; j++)
                nr[j] = __ldg(table + tbase + split + NSPLIT * min(t + 2 * STRIDE + j, tmax));
        }

        // per-lane partial dots for all TT tokens (max shfl-chain ILP)
        float x[TT][GG];
#pragma unroll
        for (int j = 0; j < TT; j++)
#pragma unroll
            for (int g = 0; g < GG; g++) x[j][g] = dot4(k[j], qv[g]);

#pragma unroll
        for (int j = 0; j < TT; j++)
#pragma unroll
            for (int g = 0; g < GG; g++)
                x[j][g] += __shfl_xor_sync(0xffffffffu, x[j][g], 1);
#pragma unroll
        for (int j = 0; j < TT; j++)
#pragma unroll
            for (int g = 0; g < GG; g++)
                x[j][g] += __shfl_xor_sync(0xffffffffu, x[j][g], 2);

        float y[TT];
#pragma unroll
        for (int j = 0; j < TT; j++) {
            float a = sel1 ? x[j][1] : x[j][0];
            float c = sel1 ? x[j][3] : x[j][2];
            y[j] = sel2 ? c : a;
        }
#pragma unroll
        for (int j = 0; j < TT; j++) y[j] += __shfl_xor_sync(0xffffffffu, y[j], 4);
#pragma unroll
        for (int j = 0; j < TT; j++) y[j] += __shfl_xor_sync(0xffffffffu, y[j], 8);
#pragma unroll
        for (int j = 0; j < TT; j++) y[j] += __shfl_xor_sync(0xffffffffu, y[j], 16);

#pragma unroll
        for (int j = 0; j < TT; j++) {
            const bool valid = (t + j) < nt;
#pragma unroll
            for (int g = 0; g < GG; g++) {
                float yg = __shfl_sync(0xffffffffu, y[j], bcast_base | g);
                float p  = valid ? exp2f(yg) : 0.f;
                l[g] += p;
                acc[g].x += p * v[j].x; acc[g].y += p * v[j].y;
                acc[g].z += p * v[j].z; acc[g].w += p * v[j].w;
            }
        }
    }

    // cross-warp merge: plain sums (no max terms)
#pragma unroll
    for (int g = 0; g < GG; g++) {
        *(float4*)&sh_acc[wid][g][lane * 4] = acc[g];
        if (lane == 0) sh_l[wid][g] = l[g];
    }
    __syncthreads();

    for (int idx = tid; idx < GG * DD; idx += NTHR) {
        const int g = idx >> 7;
        const int d = idx & (DD - 1);
        float A = 0.f;
#pragma unroll
        for (int w = 0; w < NWARP; w++) A += sh_acc[w][g][d];
        const size_t po = (size_t)split * BB * HQ + (size_t)b * HQ + h * GG + g;
        g_pacc[po * DD + d] = A;
        if (d == 0) {
            float L = 0.f;
#pragma unroll
            for (int w = 0; w < NWARP; w++) L += sh_l[w][g];
            g_pl[po] = L;
        }
    }

    // ── fused combine: last CTA per (b,h) reduces all NSPLIT partials ──
    __threadfence();                       // release our partial writes
    __syncthreads();
    if (tid == 0)
        sh_ticket = atomicAdd(&g_cnt[b * HKV + h], 1u);
    __syncthreads();
    if (sh_ticket != NSPLIT - 1) return;   // not last

    if (tid == 0) g_cnt[b * HKV + h] = 0;  // self-reset for next graph replay
    __threadfence();                       // acquire: other CTAs' partials visible

    for (int idx = tid; idx < GG * DD; idx += NTHR) {
        const int g = idx >> 7;
        const int d = idx & (DD - 1);
        const size_t base = (size_t)b * HQ + h * GG + g;
        float A = 0.f, L = 0.f;
#pragma unroll
        for (int i = 0; i < NSPLIT; i++) {
            const size_t po = (size_t)i * BB * HQ + base;
            A += g_pacc[po * DD + d];
            L += g_pl[po];
        }
        out[base * DD + d] = A / L;
    }
}

extern "C" void kernel_launch(void* const* d_in, const int* in_sizes, int n_in,
                              void* d_out, int out_size)
{
    const float* xq      = (const float*)d_in[0];
    const float* xk      = (const float*)d_in[1];
    const float* xv      = (const float*)d_in[2];
    const float* kv      = (const float*)d_in[3];
    const int*   cur_sel = (const int*)d_in[4];
    const int*   table   = (const int*)d_in[5];
    const int*   seqlens = (const int*)d_in[6];
    float*       out     = (float*)d_out;

    dim3 grid(NSPLIT, HKV, BB);
    attn_fused<<<grid, NTHR>>>(xq, xk, xv, kv, cur_sel, table, seqlens, out);
}

// round 7
// speedup vs baseline: 1.0810x; 1.0810x over previous
#include <cuda_runtime.h>

// Problem constants
#define BB     32
#define HQ     32
#define HKV    8
#define DD     128
#define SS     4096
#define GG     4          // HQ / HKV
#define NSPLIT 16         // interleaved: split i takes tokens s ≡ i (mod 16)
#define NWARP  4
#define NTHR   128
#define SLOTS  (NWARP * 2)   // 8 tokens per CTA iteration (2 per warp: 16-lane groups)

// Split-KV partial scratch (allocation-free: __device__ globals)
__device__ float g_pacc[(size_t)NSPLIT * BB * HQ * DD];   // 8.4 MB
__device__ float g_pl[NSPLIT * BB * HQ];

__device__ __forceinline__ float dot4(float4 a, float4 b) {
    return a.x*b.x + a.y*b.y + a.z*b.z + a.w*b.w;
}

__global__ __launch_bounds__(NTHR, 4) void attn_partial(
    const float* __restrict__ xq, const float* __restrict__ xk,
    const float* __restrict__ xv, const float* __restrict__ kv,
    const int* __restrict__ cur_sel, const int* __restrict__ table,
    const int* __restrict__ seqlens)
{
    const int split = blockIdx.x;
    const int h     = blockIdx.y;
    const int b     = blockIdx.z;

    const int seq_len = seqlens[b];
    // Interleaved split: tokens s = split + NSPLIT * t, t in [0, nt).
    // seq_len >= 1024 > NSPLIT, so nt >= 64: every split is always active.
    const int nt  = (seq_len - split + NSPLIT - 1) / NSPLIT;
    const int cur = cur_sel[b];

    const int tid  = threadIdx.x;
    const int wid  = tid >> 5;
    const int lane = tid & 31;
    const int sub  = lane & 15;          // position within 16-lane group
    const int grp  = lane >> 4;          // 0 or 1: which token this half-warp owns
    const int myslot = wid * 2 + grp;    // 0..7 token slot within CTA iteration

    __shared__ float sh_acc[NWARP][GG][DD];   // 8 KB
    __shared__ float sh_l[NWARP][GG];

    // softmax in log2 domain; fold scale*log2e into Q.
    // Lane owns dims {c*64 + sub*4 .. +3} for c in {0,1}  (byte offs sub*16 + c*256)
    const float scale = 0.08838834764831845f * 1.4426950408889634f;
    float4 qv[GG][2];
#pragma unroll
    for (int g = 0; g < GG; g++)
#pragma unroll
        for (int c = 0; c < 2; c++) {
            float4 q = *(const float4*)(xq + ((size_t)b * HQ + h * GG + g) * DD
                                        + c * 64 + sub * 4);
            q.x *= scale; q.y *= scale; q.z *= scale; q.w *= scale;
            qv[g][c] = q;
        }

    float  l[GG];
    float4 acc[GG][2];
#pragma unroll
    for (int g = 0; g < GG; g++) {
        l[g] = 0.f;
        acc[g][0] = make_float4(0.f,0.f,0.f,0.f);
        acc[g][1] = make_float4(0.f,0.f,0.f,0.f);
    }

    const int    tbase = b * SS;
    const size_t qkvo  = ((size_t)b * HKV + h) * DD;
    const size_t rowsz = (size_t)(2 * HKV * DD);
    const size_t koff  = (size_t)h * DD;
    const size_t voff  = (size_t)(HKV + h) * DD;

    const int tmax  = nt - 1;
    const int niter = (nt + SLOTS - 1) / SLOTS;

    // depth-2 rotated prefetch: stage st holds iteration (i) K/V; nr[st] holds
    // the row index for iteration (i+2)'s token.
    float4 bk[2][2], bv[2][2];
    int    nr[2];

#pragma unroll
    for (int st = 0; st < 2; st++) {
        int t = min(st * SLOTS + myslot, tmax);
        int r = __ldg(table + tbase + split + NSPLIT * t);
        const float* kp = (r == cur) ? xk + qkvo : kv + (size_t)r * rowsz + koff;
        const float* vp = (r == cur) ? xv + qkvo : kv + (size_t)r * rowsz + voff;
        bk[st][0] = *(const float4*)(kp + sub * 4);
        bk[st][1] = *(const float4*)(kp + sub * 4 + 64);
        bv[st][0] = *(const float4*)(vp + sub * 4);
        bv[st][1] = *(const float4*)(vp + sub * 4 + 64);
    }
#pragma unroll
    for (int st = 0; st < 2; st++)
        nr[st] = __ldg(table + tbase + split
                       + NSPLIT * min((2 + st) * SLOTS + myslot, tmax));

    for (int i = 0; i < niter; i += 2) {
#pragma unroll
        for (int st = 0; st < 2; st++) {
            const int it = i + st;
            if (st == 1 && it >= niter) break;

            // grab current stage
            float4 k0 = bk[st][0], k1 = bk[st][1];
            float4 v0 = bv[st][0], v1 = bv[st][1];

            // refill stage with iteration (it+2); row prefetched, clamp-safe
            {
                int r = nr[st];
                const float* kp = (r == cur) ? xk + qkvo : kv + (size_t)r * rowsz + koff;
                const float* vp = (r == cur) ? xv + qkvo : kv + (size_t)r * rowsz + voff;
                bk[st][0] = *(const float4*)(kp + sub * 4);
                bk[st][1] = *(const float4*)(kp + sub * 4 + 64);
                bv[st][0] = *(const float4*)(vp + sub * 4);
                bv[st][1] = *(const float4*)(vp + sub * 4 + 64);
                nr[st] = __ldg(table + tbase + split
                               + NSPLIT * min((it + 4) * SLOTS + myslot, tmax));
            }

            // dot for 4 heads over this lane's 8 dims
            float x[GG];
#pragma unroll
            for (int g = 0; g < GG; g++)
                x[g] = dot4(k0, qv[g][0]) + dot4(k1, qv[g][1]);

            // 16-lane group reduce: 4 levels, all lanes end with the full sum
#pragma unroll
            for (int g = 0; g < GG; g++) x[g] += __shfl_xor_sync(0xffffffffu, x[g], 1);
#pragma unroll
            for (int g = 0; g < GG; g++) x[g] += __shfl_xor_sync(0xffffffffu, x[g], 2);
#pragma unroll
            for (int g = 0; g < GG; g++) x[g] += __shfl_xor_sync(0xffffffffu, x[g], 4);
#pragma unroll
            for (int g = 0; g < GG; g++) x[g] += __shfl_xor_sync(0xffffffffu, x[g], 8);

            const bool valid = (it * SLOTS + myslot) < nt;
#pragma unroll
            for (int g = 0; g < GG; g++) {
                float p = valid ? exp2f(x[g]) : 0.f;
                l[g] += p;
                acc[g][0].x += p * v0.x; acc[g][0].y += p * v0.y;
                acc[g][0].z += p * v0.z; acc[g][0].w += p * v0.w;
                acc[g][1].x += p * v1.x; acc[g][1].y += p * v1.y;
                acc[g][1].z += p * v1.z; acc[g][1].w += p * v1.w;
            }
        }
    }

    // merge the two 16-lane groups (different tokens, same dims): xor 16
#pragma unroll
    for (int g = 0; g < GG; g++) {
#pragma unroll
        for (int c = 0; c < 2; c++) {
            acc[g][c].x += __shfl_xor_sync(0xffffffffu, acc[g][c].x, 16);
            acc[g][c].y += __shfl_xor_sync(0xffffffffu, acc[g][c].y, 16);
            acc[g][c].z += __shfl_xor_sync(0xffffffffu, acc[g][c].z, 16);
            acc[g][c].w += __shfl_xor_sync(0xffffffffu, acc[g][c].w, 16);
        }
        l[g] += __shfl_xor_sync(0xffffffffu, l[g], 16);
    }

    // lanes 0..15 write this warp's partial to smem
    if (grp == 0) {
#pragma unroll
        for (int g = 0; g < GG; g++) {
#pragma unroll
            for (int c = 0; c < 2; c++)
                *(float4*)&sh_acc[wid][g][c * 64 + sub * 4] = acc[g][c];
            if (sub == 0) sh_l[wid][g] = l[g];
        }
    }
    __syncthreads();

    // cross-warp merge + write partials
    for (int idx = tid; idx < GG * DD; idx += NTHR) {
        const int g = idx >> 7;
        const int d = idx & (DD - 1);
        float A = 0.f;
#pragma unroll
        for (int w = 0; w < NWARP; w++) A += sh_acc[w][g][d];
        const size_t po = (size_t)split * BB * HQ + (size_t)b * HQ + h * GG + g;
        g_pacc[po * DD + d] = A;
        if (d == 0) {
            float L = 0.f;
#pragma unroll
            for (int w = 0; w < NWARP; w++) L += sh_l[w][g];
            g_pl[po] = L;
        }
    }
}

__global__ __launch_bounds__(DD) void attn_combine(float* __restrict__ out)
{
    const int bq = blockIdx.x;      // b*HQ + qh
    const int d  = threadIdx.x;

    // Every split is active (interleaved, seq_len >= 1024) -> all slots written
    // every launch; fully unrolled unconditional loads, 32 LDGs in flight.
    float L = 0.f, A = 0.f;
#pragma unroll
    for (int i = 0; i < NSPLIT; i++) {
        const size_t po = (size_t)i * BB * HQ + bq;
        L += g_pl[po];
        A += g_pacc[po * DD + d];
    }
    out[(size_t)bq * DD + d] = A / L;
}

extern "C" void kernel_launch(void* const* d_in, const int* in_sizes, int n_in,
                              void* d_out, int out_size)
{
    const float* xq      = (const float*)d_in[0];
    const float* xk      = (const float*)d_in[1];
    const float* xv      = (const float*)d_in[2];
    const float* kv      = (const float*)d_in[3];
    const int*   cur_sel = (const int*)d_in[4];
    const int*   table   = (const int*)d_in[5];
    const int*   seqlens = (const int*)d_in[6];
    float*       out     = (float*)d_out;

    dim3 grid(NSPLIT, HKV, BB);
    attn_partial<<<grid, NTHR>>>(xq, xk, xv, kv, cur_sel, table, seqlens);
    attn_combine<<<BB * HQ, DD>>>(out);
}